// round 12
// baseline (speedup 1.0000x reference)
#include <cuda_runtime.h>
#include <cstdint>

// Problem constants
#define IN_F    2048
#define OUT_F   4096
#define BATCHN  131072
#define IN_F4   (IN_F / 4)        // 512 float4 columns

#define NTHREADS 512              // 16 warps per block

// Fused-kernel block layout (producer bids < consumer bids; low bids are
// wave-1 resident deterministically => deadlock-free spins).
#define NFOLD    16               // folder blocks (bids 0..15)
#define BID_BIAS 16
#define NRED     1024             // weight reducers (4 rows x 512 f4cols each)
#define BID_RED0 17
#define BID_GEMV0 (BID_RED0 + NRED)          // 1041
#define NGEMV    (BATCHN / 16)               // 8192 (16 rows per block)
#define GRID_TOTAL (BID_GEMV0 + NGEMV)       // 9233

#define NSLICE   1024             // 4096 rows / 4 rows per reducer slice

// Scratch globals (allocation-free, fully rewritten every launch =>
// graph-replay deterministic).
__device__ float4 g_partial4[NSLICE * IN_F4];   // 8 MiB
__device__ float  g_wsum[IN_F];
__device__ float  g_bsum;
__device__ int    g_red_done;     // -> NRED
__device__ int    g_fold_done;    // -> NFOLD + 1

__global__ void init_kernel() {
    g_red_done  = 0;
    g_fold_done = 0;
}

// ---------------------------------------------------------------------------
__global__ __launch_bounds__(NTHREADS) void fused_kernel(const float4* __restrict__ w4,
                                                         const float*  __restrict__ x,
                                                         const float*  __restrict__ bias,
                                                         float* __restrict__ out) {
    __shared__ float4 sw[IN_F4];          // 8 KB  (gemv staging / folder scratch)
    __shared__ float4 sbuf[4 * IN_F4];    // 32 KB (reducer cp.async landing)
    const int tid = threadIdx.x;
    const int bid = blockIdx.x;

    // ======================== GEMV blocks (hot path) ========================
    if (bid >= BID_GEMV0) {
        const int gvb  = bid - BID_GEMV0;
        const int warp = tid >> 5;
        const int lane = tid & 31;
        const int row  = gvb * 16 + warp;
        const float4* xr = reinterpret_cast<const float4*>(x + (size_t)row * IN_F);

        // Issue first half of this thread's REAL x loads before waiting.
        // Register-destined, single-use: overlaps the weight reduction
        // without polluting L2.
        float4 xa[8];
        #pragma unroll
        for (int i = 0; i < 8; ++i) {
            xa[i] = xr[i * 32 + lane];
        }

        // Wait for w_sum + b_sum (loads above stay in flight).
        if (tid == 0) {
            int backoff = 32;
            while (*(volatile int*)&g_fold_done != (NFOLD + 1)) {
                __nanosleep(backoff);
                if (backoff < 1024) backoff <<= 1;
            }
            __threadfence();
        }
        __syncthreads();

        // Stage w_sum into shared (512 threads -> one pass).
        sw[tid] = reinterpret_cast<const float4*>(g_wsum)[tid];
        __syncthreads();
        const float bsum = g_bsum;

        float acc = 0.0f;
        #pragma unroll
        for (int i = 0; i < 8; ++i) {           // preloaded half
            const float4 wv = sw[i * 32 + lane];
            acc += xa[i].x * wv.x + xa[i].y * wv.y + xa[i].z * wv.z + xa[i].w * wv.w;
        }
        #pragma unroll
        for (int i = 8; i < 16; ++i) {          // streamed half
            const float4 xv = xr[i * 32 + lane];
            const float4 wv = sw[i * 32 + lane];
            acc += xv.x * wv.x + xv.y * wv.y + xv.z * wv.z + xv.w * wv.w;
        }
        #pragma unroll
        for (int off = 16; off > 0; off >>= 1) {
            acc += __shfl_xor_sync(0xFFFFFFFFu, acc, off);
        }
        if (lane == 0) out[row] = acc + bsum;
        return;
    }

    // ======================== Weight reducer blocks ========================
    // cp.async (LDGSTS) pipeline: depth-uncapped outstanding copies sidestep
    // the ptxas load-chain collapsing that limited the LDG version to ~3.6 TB/s
    // (R3/R6: regs 31/32 => MLP ~6). 4 rows x 8 KB land in SMEM, then a short
    // LDS reduce produces the partial.
    if (bid >= BID_RED0) {
        const int s = bid - BID_RED0;          // 4-row slice, all 512 f4-cols
        const float4* wp = w4 + (size_t)(s * 4) * IN_F4 + tid;

        unsigned int sb;
        asm("{ .reg .u64 t; cvta.to.shared.u64 t, %1; cvt.u32.u64 %0, t; }"
            : "=r"(sb) : "l"(sbuf));

        #pragma unroll
        for (int r = 0; r < 4; ++r) {
            const unsigned int dst = sb + (unsigned int)((r * IN_F4 + tid) * 16);
            const float4*      src = wp + (size_t)r * IN_F4;
            asm volatile("cp.async.cg.shared.global [%0], [%1], 16;"
                         :: "r"(dst), "l"(src));
        }
        asm volatile("cp.async.commit_group;");
        asm volatile("cp.async.wait_group 0;");
        __syncwarp();

        const float4 a = sbuf[0 * IN_F4 + tid];
        const float4 b = sbuf[1 * IN_F4 + tid];
        const float4 c = sbuf[2 * IN_F4 + tid];
        const float4 d = sbuf[3 * IN_F4 + tid];
        float4 acc;
        acc.x = (a.x + b.x) + (c.x + d.x);
        acc.y = (a.y + b.y) + (c.y + d.y);
        acc.z = (a.z + b.z) + (c.z + d.z);
        acc.w = (a.w + b.w) + (c.w + d.w);
        g_partial4[s * IN_F4 + tid] = acc;
        __threadfence();
        __syncthreads();
        if (tid == 0) atomicAdd(&g_red_done, 1);
        return;
    }

    // ======================== Bias block ========================
    if (bid == BID_BIAS) {
        __shared__ float red[NTHREADS];
        float s = 0.0f;
        #pragma unroll
        for (int i = 0; i < OUT_F / NTHREADS; ++i) s += bias[i * NTHREADS + tid];
        red[tid] = s;
        __syncthreads();
        #pragma unroll
        for (int stride = NTHREADS / 2; stride > 0; stride >>= 1) {
            if (tid < stride) red[tid] += red[tid + stride];
            __syncthreads();
        }
        if (tid == 0) {
            g_bsum = red[0];
            __threadfence();
            atomicAdd(&g_fold_done, 1);
        }
        return;
    }

    // ======================== Folder blocks (bids 0..15) ========================
    {
        if (tid == 0) {
            int backoff = 32;
            while (*(volatile int*)&g_red_done != NRED) {
                __nanosleep(backoff);
                if (backoff < 1024) backoff <<= 1;
            }
            __threadfence();
        }
        __syncthreads();

        const int lane = tid & 31;
        const int wrp  = tid >> 5;           // 16 warps = 16 slice groups
        const int col  = bid * 32 + lane;    // this block's 32 float4 columns

        // Each warp folds 64 of the 1024 slices (p = wrp + 16*j), L2-resident.
        float4 acc = make_float4(0.f, 0.f, 0.f, 0.f);
        #pragma unroll 8
        for (int j = 0; j < 64; ++j) {
            const float4 v = g_partial4[(wrp + 16 * j) * IN_F4 + col];
            acc.x += v.x; acc.y += v.y; acc.z += v.z; acc.w += v.w;
        }

        float4* sh = sw;                     // 16*32 float4 = 8 KB
        sh[wrp * 32 + lane] = acc;
        __syncthreads();
        if (wrp == 0) {
            float4 t = sh[lane];
            #pragma unroll
            for (int p = 1; p < 16; ++p) {
                const float4 v = sh[p * 32 + lane];
                t.x += v.x; t.y += v.y; t.z += v.z; t.w += v.w;
            }
            reinterpret_cast<float4*>(g_wsum)[col] = t;
            __threadfence();
        }
        __syncthreads();
        if (tid == 0) atomicAdd(&g_fold_done, 1);
        return;
    }
}

// ---------------------------------------------------------------------------
extern "C" void kernel_launch(void* const* d_in, const int* in_sizes, int n_in,
                              void* d_out, int out_size) {
    const float* x      = (const float*)d_in[0];  // (131072, 2048)
    const float* weight = (const float*)d_in[1];  // (4096, 2048)
    const float* bias   = (const float*)d_in[2];  // (4096,)
    float* out = (float*)d_out;                   // (131072, 1)

    (void)in_sizes; (void)n_in; (void)out_size;

    init_kernel<<<1, 1>>>();
    fused_kernel<<<GRID_TOTAL, NTHREADS>>>(reinterpret_cast<const float4*>(weight),
                                           x, bias, out);
}

// round 13
// speedup vs baseline: 1.0518x; 1.0518x over previous
#include <cuda_runtime.h>

// Problem constants
#define IN_F    2048
#define OUT_F   4096
#define BATCHN  131072
#define IN_F4   (IN_F / 4)        // 512 float4 columns

// Fused-kernel block layout (producer bids < consumer bids; low bids are
// wave-1 resident deterministically => deadlock-free spins).
#define NFOLD    16               // folder blocks (bids 0..15)
#define BID_BIAS 16
#define NRED     512              // weight reducers (bids 17..528), 16 rows each
#define BID_RED0 17
#define BID_GEMV0 (BID_RED0 + NRED)          // 529
#define NGEMV    (BATCHN / 8)                // 16384
#define GRID_TOTAL (BID_GEMV0 + NGEMV)       // 16913

#define NSLICE   256              // 4096 rows / 16 rows per reducer slice

// Scratch globals (allocation-free, fully rewritten every launch =>
// graph-replay deterministic).
__device__ float4 g_partial4[NSLICE * IN_F4];   // 2 MiB
__device__ float  g_wsum[IN_F];
__device__ float  g_bsum;
__device__ int    g_red_done;     // -> NRED
__device__ int    g_fold_done;    // -> NFOLD + 1

__global__ void init_kernel() {
    g_red_done  = 0;
    g_fold_done = 0;
}

// Forced-MLP vector load: inline asm pins 4 float regs per load, so ptxas
// cannot collapse a batch of these into a short-register rolling chain
// (the failure seen in R3/R6/R8 where regs=31/32 => MLP~6 => 3.6 TB/s).
__device__ __forceinline__ float4 ldg_nc_v4(const float4* p) {
    float4 v;
    asm volatile("ld.global.nc.v4.f32 {%0,%1,%2,%3}, [%4];"
                 : "=f"(v.x), "=f"(v.y), "=f"(v.z), "=f"(v.w)
                 : "l"(p));
    return v;
}

// ---------------------------------------------------------------------------
__global__ __launch_bounds__(256) void fused_kernel(const float4* __restrict__ w4,
                                                    const float*  __restrict__ x,
                                                    const float*  __restrict__ bias,
                                                    float* __restrict__ out) {
    __shared__ float4 sw[IN_F4];      // 8 KB
    const int tid = threadIdx.x;
    const int bid = blockIdx.x;

    // ======================== GEMV blocks (hot path) ========================
    if (bid >= BID_GEMV0) {
        const int gvb  = bid - BID_GEMV0;
        const int warp = tid >> 5;
        const int lane = tid & 31;
        const int row  = gvb * 8 + warp;
        const float4* xr = reinterpret_cast<const float4*>(x + (size_t)row * IN_F);

        // Issue first half of this thread's REAL x loads before waiting.
        // Register-destined, single-use: overlaps the weight reduction
        // without polluting L2.
        float4 xa[8];
        #pragma unroll
        for (int i = 0; i < 8; ++i) {
            xa[i] = xr[i * 32 + lane];
        }

        // Wait for w_sum + b_sum (loads above stay in flight).
        if (tid == 0) {
            int backoff = 32;
            while (*(volatile int*)&g_fold_done != (NFOLD + 1)) {
                __nanosleep(backoff);
                if (backoff < 256) backoff <<= 1;
            }
            __threadfence();
        }
        __syncthreads();

        // Stage w_sum into shared.
        #pragma unroll
        for (int i = 0; i < IN_F4 / 256; ++i) {
            sw[i * 256 + tid] = reinterpret_cast<const float4*>(g_wsum)[i * 256 + tid];
        }
        __syncthreads();
        const float bsum = g_bsum;

        float acc = 0.0f;
        #pragma unroll
        for (int i = 0; i < 8; ++i) {           // preloaded half
            const float4 wv = sw[i * 32 + lane];
            acc += xa[i].x * wv.x + xa[i].y * wv.y + xa[i].z * wv.z + xa[i].w * wv.w;
        }
        #pragma unroll
        for (int i = 8; i < 16; ++i) {          // streamed half
            const float4 xv = xr[i * 32 + lane];
            const float4 wv = sw[i * 32 + lane];
            acc += xv.x * wv.x + xv.y * wv.y + xv.z * wv.z + xv.w * wv.w;
        }
        #pragma unroll
        for (int off = 16; off > 0; off >>= 1) {
            acc += __shfl_xor_sync(0xFFFFFFFFu, acc, off);
        }
        if (lane == 0) out[row] = acc + bsum;
        return;
    }

    // ======================== Weight reducer blocks ========================
    if (bid >= BID_RED0) {
        const int r  = bid - BID_RED0;
        const int cg = r & 1;              // column group
        const int s  = r >> 1;             // 16-row slice
        const int c  = cg * 256 + tid;
        const float4* wp = w4 + (size_t)(s * 16) * IN_F4 + c;

        float4 acc = make_float4(0.f, 0.f, 0.f, 0.f);
        #pragma unroll
        for (int b = 0; b < 2; ++b) {
            // 8 asm loads with pinned destination registers -> MLP >= 8.
            const float4* p = wp + (size_t)(b * 8) * IN_F4;
            float4 t0 = ldg_nc_v4(p + 0 * IN_F4);
            float4 t1 = ldg_nc_v4(p + 1 * IN_F4);
            float4 t2 = ldg_nc_v4(p + 2 * IN_F4);
            float4 t3 = ldg_nc_v4(p + 3 * IN_F4);
            float4 t4 = ldg_nc_v4(p + 4 * IN_F4);
            float4 t5 = ldg_nc_v4(p + 5 * IN_F4);
            float4 t6 = ldg_nc_v4(p + 6 * IN_F4);
            float4 t7 = ldg_nc_v4(p + 7 * IN_F4);
            t0.x += t1.x; t0.y += t1.y; t0.z += t1.z; t0.w += t1.w;
            t2.x += t3.x; t2.y += t3.y; t2.z += t3.z; t2.w += t3.w;
            t4.x += t5.x; t4.y += t5.y; t4.z += t5.z; t4.w += t5.w;
            t6.x += t7.x; t6.y += t7.y; t6.z += t7.z; t6.w += t7.w;
            t0.x += t2.x; t0.y += t2.y; t0.z += t2.z; t0.w += t2.w;
            t4.x += t6.x; t4.y += t6.y; t4.z += t6.z; t4.w += t6.w;
            acc.x += t0.x + t4.x;
            acc.y += t0.y + t4.y;
            acc.z += t0.z + t4.z;
            acc.w += t0.w + t4.w;
        }
        g_partial4[s * IN_F4 + c] = acc;
        __threadfence();
        __syncthreads();
        if (tid == 0) atomicAdd(&g_red_done, 1);
        return;
    }

    // ======================== Bias block ========================
    if (bid == BID_BIAS) {
        __shared__ float red[256];
        float s = 0.0f;
        #pragma unroll
        for (int i = 0; i < OUT_F / 256; ++i) s += bias[i * 256 + tid];
        red[tid] = s;
        __syncthreads();
        #pragma unroll
        for (int stride = 128; stride > 0; stride >>= 1) {
            if (tid < stride) red[tid] += red[tid + stride];
            __syncthreads();
        }
        if (tid == 0) {
            g_bsum = red[0];
            __threadfence();
            atomicAdd(&g_fold_done, 1);
        }
        return;
    }

    // ======================== Folder blocks (bids 0..15) ========================
    {
        if (tid == 0) {
            int backoff = 32;
            while (*(volatile int*)&g_red_done != NRED) {
                __nanosleep(backoff);
                if (backoff < 256) backoff <<= 1;
            }
            __threadfence();
        }
        __syncthreads();

        const int lane = tid & 31;
        const int wrp  = tid >> 5;           // 8 warps = 8 slice groups
        const int col  = bid * 32 + lane;    // this block's 32 float4 columns

        float4 acc = make_float4(0.f, 0.f, 0.f, 0.f);
        #pragma unroll 8
        for (int j = 0; j < 32; ++j) {       // slices p = wrp + 8*j
            const float4 v = g_partial4[(wrp + 8 * j) * IN_F4 + col];
            acc.x += v.x; acc.y += v.y; acc.z += v.z; acc.w += v.w;
        }

        float4* sh = sw;                     // 8*32 float4 = 4 KB
        sh[wrp * 32 + lane] = acc;
        __syncthreads();
        if (wrp == 0) {
            float4 t = sh[lane];
            #pragma unroll
            for (int p = 1; p < 8; ++p) {
                const float4 v = sh[p * 32 + lane];
                t.x += v.x; t.y += v.y; t.z += v.z; t.w += v.w;
            }
            reinterpret_cast<float4*>(g_wsum)[col] = t;
            __threadfence();
        }
        __syncthreads();
        if (tid == 0) atomicAdd(&g_fold_done, 1);
        return;
    }
}

// ---------------------------------------------------------------------------
extern "C" void kernel_launch(void* const* d_in, const int* in_sizes, int n_in,
                              void* d_out, int out_size) {
    const float* x      = (const float*)d_in[0];  // (131072, 2048)
    const float* weight = (const float*)d_in[1];  // (4096, 2048)
    const float* bias   = (const float*)d_in[2];  // (4096,)
    float* out = (float*)d_out;                   // (131072, 1)

    (void)in_sizes; (void)n_in; (void)out_size;

    init_kernel<<<1, 1>>>();
    fused_kernel<<<GRID_TOTAL, 256>>>(reinterpret_cast<const float4*>(weight),
                                      x, bias, out);
}